// round 12
// baseline (speedup 1.0000x reference)
#include <cuda_runtime.h>
#include <cuda_fp16.h>
#include <cstdint>

#define Cc   256
#define Bn   8
#define Hh   128
#define Ww   128
#define NWw  512
#define HW   (Hh*Ww)
#define NPIX (Bn*HW)
#define EPSf 1e-5f

typedef unsigned long long ull;

// ---- scratch ---------------------------------------------------------------
__device__ float  g_ps [Cc*Bn];
__device__ float  g_ps2[Cc*Bn];
__device__ float  g_scale[Cc];
__device__ float  g_shift[Cc];
__device__ __half g_w1h[Cc * NWw];     // [c][j] K-major A operand
__device__ float  g_lwf[32][176];      // per chunk: 16j x (9 folded w + bias), [160..167]=xpad

__device__ __forceinline__ uint32_t smem_u32(const void* p) {
    uint32_t a;
    asm("{ .reg .u64 t; cvta.to.shared.u64 t, %1; cvt.u32.u64 %0, t; }"
        : "=r"(a) : "l"(p));
    return a;
}

#define PACK2(d, lo, hi) asm("mov.b64 %0, {%1, %2};" : "=l"(d) : "f"(lo), "f"(hi))
#define PACKB(d, v)      asm("mov.b64 %0, {%1, %1};" : "=l"(d) : "f"(v))
#define UNPACK2(lo, hi, s) asm("mov.b64 {%0, %1}, %2;" : "=f"(lo), "=f"(hi) : "l"(s))
#define FMA2(acc, a, b)  asm("fma.rn.f32x2 %0, %1, %2, %0;" : "+l"(acc) : "l"(a), "l"(b))

// ---------------------------------------------------------------------------
// Stats (2-stage, deterministic)
// ---------------------------------------------------------------------------
__global__ __launch_bounds__(256) void stats_part(const float* __restrict__ x) {
    int c = blockIdx.x, b = blockIdx.y, tid = threadIdx.x;
    const float4* p = (const float4*)(x + ((size_t)(b * Cc + c)) * HW);
    float s = 0.f, s2 = 0.f;
    #pragma unroll 4
    for (int i = tid; i < HW / 4; i += 256) {
        float4 v = __ldg(p + i);
        s  += v.x + v.y + v.z + v.w;
        s2 += v.x*v.x + v.y*v.y + v.z*v.z + v.w*v.w;
    }
    __shared__ float sh[256], sh2[256];
    sh[tid] = s; sh2[tid] = s2;
    __syncthreads();
    for (int off = 128; off > 0; off >>= 1) {
        if (tid < off) { sh[tid] += sh[tid+off]; sh2[tid] += sh2[tid+off]; }
        __syncthreads();
    }
    if (tid == 0) { g_ps[c*Bn + b] = sh[0]; g_ps2[c*Bn + b] = sh2[0]; }
}

__global__ void finalize_stats(const float* __restrict__ gamma,
                               const float* __restrict__ beta) {
    int c = threadIdx.x;
    float s = 0.f, s2 = 0.f;
    #pragma unroll
    for (int b = 0; b < Bn; b++) { s += g_ps[c*Bn+b]; s2 += g_ps2[c*Bn+b]; }
    float n = (float)(Bn * HW);
    float mean = s / n;
    float var  = s2 / n - mean * mean;
    float sc   = gamma[c] * rsqrtf(var + EPSf);
    g_scale[c] = sc;
    g_shift[c] = beta[c] - mean * sc;
}

__global__ void w1half(const float* __restrict__ w1) {
    int i = (blockIdx.x * 256 + threadIdx.x) * 4;
    float4 v = __ldg((const float4*)(w1 + i));
    __half2 a = __floats2half2_rn(v.x, v.y);
    __half2 b = __floats2half2_rn(v.z, v.w);
    uint2 o = make_uint2(*(uint32_t*)&a, *(uint32_t*)&b);
    *(uint2*)(g_w1h + i) = o;
}

// fold BN into stencil weights (validated in round 6)
__global__ void prep_lwf(const float* __restrict__ lbp) {
    int j  = threadIdx.x;                 // 512 threads, 1 block
    int ci = j >> 1;
    int kc = j >> 4, jl = j & 15;
    float sc = g_scale[ci], sf = g_shift[ci];
    float s = 0.f;
    #pragma unroll
    for (int t = 0; t < 9; t++) {
        float w = __ldg(lbp + j * 9 + t);
        g_lwf[kc][jl * 10 + t] = w * sc;
        s += w;
    }
    g_lwf[kc][jl * 10 + 9] = sf * s;
    if (j < Cc)
        g_lwf[j >> 3][160 + (j & 7)] = -g_shift[j] / g_scale[j];
}

// ---------------------------------------------------------------------------
// Fused kernel: BN+dw3x3+relu+1x1+bias+residual.
// Block: 256 thr (8 warps 4Mx2N), tile M=256 x N=64 px, 32 K-chunks of 16 j.
// 3-stage cp.async pipeline; stencil on raw x with folded weights.
// ---------------------------------------------------------------------------
#define STG   17920           // per-stage bytes (128-aligned)
#define O_XS  0               // 8ch x 3r x 72 f32 = 6912
#define O_AW  6912            // 256c x 16j f16    = 8192
#define O_YS  15104           // 16j x 64px f16    = 2048
#define O_LW  17152           // 176 f32           = 704
#define SMEM_TOT (3 * STG)    // 53760

__global__ __launch_bounds__(256, 2)
void fused_kernel(const float* __restrict__ x, const float* __restrict__ b1,
                  float* __restrict__ out) {
    extern __shared__ __align__(128) char dsm[];
    const uint32_t SB = smem_u32(dsm);

    const int tid  = threadIdx.x;
    const int wid  = tid >> 5, lane = tid & 31;
    const int wm   = wid >> 1;                 // 0..3 (M)
    const int wn   = wid & 1;                  // 0..1 (N)
    const int pt   = blockIdx.x;               // 0..2047
    const int b    = pt >> 8;
    const int tile = pt & 255;
    const int h    = tile >> 1;
    const int col0 = (tile & 1) * 64;
    const int hedge = (h == 0) ? 0 : ((h == Hh - 1) ? 2 : -1);

    float acc[4][4][4];
    #pragma unroll
    for (int mi = 0; mi < 4; mi++)
        #pragma unroll
        for (int ni = 0; ni < 4; ni++)
            #pragma unroll
            for (int q = 0; q < 4; q++) acc[mi][ni][q] = 0.f;

    // ---- async fill of stage st with chunk kc ----
    auto fill = [&](int st, int kc) {
        const uint32_t base = SB + st * STG;
        const int cbase = kc * 8;
        // xs: 8ch x 3r x 16 float4 (rows clamped; edge rows fixed up later)
        #pragma unroll
        for (int i = 0; i < 2; i++) {
            int idx = tid + i * 256;
            if (idx < 384) {
                int ci  = idx / 48;
                int rem = idx - ci * 48;
                int r   = rem >> 4, q = rem & 15;
                int hh  = h - 1 + r;
                hh = hh < 0 ? 0 : (hh > Hh - 1 ? Hh - 1 : hh);
                const float* src = x + (((size_t)(b * Cc + cbase + ci)) << 14)
                                     + hh * Ww + col0 + q * 4;
                uint32_t dst = base + O_XS + ((ci * 3 + r) * 72 + 4 + q * 4) * 4;
                asm volatile("cp.async.cg.shared.global [%0], [%1], 16;"
                             :: "r"(dst), "l"(src));
            }
        }
        // halo columns (4B, zfill when OOB)
        if (tid < 48) {
            int side = tid >= 24;
            int t2 = side ? tid - 24 : tid;
            int ci = t2 / 3, r = t2 - ci * 3;
            int hh = h - 1 + r;
            hh = hh < 0 ? 0 : (hh > Hh - 1 ? Hh - 1 : hh);
            int gcol = side ? (col0 + 64) : (col0 - 1);
            int ok = ((unsigned)gcol < (unsigned)Ww) ? 4 : 0;
            int gc = ok ? gcol : 0;
            const float* src = x + (((size_t)(b * Cc + cbase + ci)) << 14)
                                 + hh * Ww + gc;
            uint32_t dst = base + O_XS + ((ci * 3 + r) * 72 + (side ? 68 : 3)) * 4;
            asm volatile("cp.async.ca.shared.global [%0], [%1], 4, %2;"
                         :: "r"(dst), "l"(src), "r"(ok));
        }
        // A: 256c x 16j halves, swizzled units
        #pragma unroll
        for (int i = 0; i < 2; i++) {
            int c = (tid >> 1) + i * 128;
            int u = tid & 1;
            int v = (((c & 3) * 2 + u) ^ ((c >> 2) & 7));
            uint32_t dst = base + O_AW + ((c >> 2) << 7) + (v << 4);
            const __half* src = g_w1h + (size_t)c * NWw + kc * 16 + u * 8;
            asm volatile("cp.async.cg.shared.global [%0], [%1], 16;"
                         :: "r"(dst), "l"(src));
        }
        // folded weights + xpad table
        if (tid < 44) {
            uint32_t dst = base + O_LW + tid * 16;
            const char* src = (const char*)g_lwf + (size_t)kc * 704 + tid * 16;
            asm volatile("cp.async.cg.shared.global [%0], [%1], 16;"
                         :: "r"(dst), "l"(src));
        }
        asm volatile("cp.async.commit_group;");
    };

    fill(0, 0);
    fill(1, 1);

    const int j  = tid >> 4;               // 0..15 (local j in chunk)
    const int pq = tid & 15;               // pixel quad
    const int ci = j >> 1;
    const bool selL = (pq == 0)  && (col0 == 0);
    const bool selR = (pq == 15) && (col0 == 64);

    for (int kc = 0; kc < 32; kc++) {
        const int st = kc - (kc / 3) * 3;                  // kc % 3
        const uint32_t base = SB + st * STG;
        if (kc < 31) asm volatile("cp.async.wait_group 1;");
        else         asm volatile("cp.async.wait_group 0;");
        __syncthreads();

        float* lwp = (float*)(dsm + st * STG + O_LW);
        float* xsp = (float*)(dsm + st * STG + O_XS);

        if (hedge >= 0) {                 // image-edge row -> xpad (rare path)
            #pragma unroll
            for (int i = 0; i < 3; i++) {
                int t2 = tid + i * 256;
                if (t2 < 528) {
                    int cc = t2 / 66, col = t2 - cc * 66;
                    xsp[(cc * 3 + hedge) * 72 + 3 + col] = lwp[160 + cc];
                }
            }
            __syncthreads();
        }

        // ---- stencil: 1 j x 4 px per thread ----
        {
            ull pw[9];
            #pragma unroll
            for (int t = 0; t < 9; t++) PACKB(pw[t], lwp[j * 10 + t]);
            float bias = lwp[j * 10 + 9];
            float xpad = lwp[160 + ci];
            ull a0, a1;
            PACKB(a0, bias);
            PACKB(a1, bias);
            const float* xb = xsp + ci * 216 + 4 * pq;
            #pragma unroll
            for (int r = 0; r < 3; r++) {
                const float* row = xb + r * 72;
                float m1 = row[3];
                float4 f = *(const float4*)(row + 4);
                float p4 = row[8];
                if (selL) m1 = xpad;
                if (selR) p4 = xpad;
                ull T0a, T1a, T2a, T1b, T2b;
                PACK2(T0a, m1, f.x);
                PACK2(T1a, f.x, f.y);
                PACK2(T2a, f.y, f.z);
                PACK2(T1b, f.z, f.w);
                PACK2(T2b, f.w, p4);
                FMA2(a0, pw[r*3+0], T0a);
                FMA2(a0, pw[r*3+1], T1a);
                FMA2(a0, pw[r*3+2], T2a);
                FMA2(a1, pw[r*3+0], T2a);
                FMA2(a1, pw[r*3+1], T1b);
                FMA2(a1, pw[r*3+2], T2b);
            }
            float s0l, s0h, s1l, s1h;
            UNPACK2(s0l, s0h, a0);
            UNPACK2(s1l, s1h, a1);
            const __half2 z2 = __floats2half2_rn(0.f, 0.f);
            __half2 h0 = __hmax2(__floats2half2_rn(s0l, s0h), z2);
            __half2 h1 = __hmax2(__floats2half2_rn(s1l, s1h), z2);
            ull packed;
            asm("mov.b64 %0, {%1, %2};" : "=l"(packed)
                : "r"(*(uint32_t*)&h0), "r"(*(uint32_t*)&h1));
            uint32_t ya = base + O_YS + (j << 7)
                        + ((((pq >> 1) ^ (j & 7))) << 4) + ((pq & 1) * 8);
            asm volatile("st.shared.b64 [%0], %1;" :: "r"(ya), "l"(packed));
        }
        __syncthreads();

        if (kc < 30) fill((kc + 2) - ((kc + 2) / 3) * 3, kc + 2);

        // ---- HMMA on chunk (K=16) ----
        {
            uint32_t a[4][4], bf[4][2];
            #pragma unroll
            for (int mi = 0; mi < 4; mi++) {
                int c = wm * 64 + mi * 16 + (lane & 15);
                int u = lane >> 4;
                int v = (((c & 3) * 2 + u) ^ ((c >> 2) & 7));
                uint32_t ad = base + O_AW + ((c >> 2) << 7) + (v << 4);
                asm volatile(
                    "ldmatrix.sync.aligned.m8n8.x4.shared.b16 {%0,%1,%2,%3}, [%4];"
                    : "=r"(a[mi][0]), "=r"(a[mi][1]), "=r"(a[mi][2]), "=r"(a[mi][3])
                    : "r"(ad));
            }
            #pragma unroll
            for (int ni = 0; ni < 4; ni++) {
                int kr = lane & 15;
                int u2 = wn * 4 + ni;
                uint32_t bd = base + O_YS + (kr << 7) + ((u2 ^ (kr & 7)) << 4);
                asm volatile(
                    "ldmatrix.sync.aligned.m8n8.x2.trans.shared.b16 {%0,%1}, [%2];"
                    : "=r"(bf[ni][0]), "=r"(bf[ni][1]) : "r"(bd));
            }
            #pragma unroll
            for (int mi = 0; mi < 4; mi++)
                #pragma unroll
                for (int ni = 0; ni < 4; ni++)
                    asm volatile(
                        "mma.sync.aligned.m16n8k16.row.col.f32.f16.f16.f32 "
                        "{%0,%1,%2,%3}, {%4,%5,%6,%7}, {%8,%9}, {%0,%1,%2,%3};"
                        : "+f"(acc[mi][ni][0]), "+f"(acc[mi][ni][1]),
                          "+f"(acc[mi][ni][2]), "+f"(acc[mi][ni][3])
                        : "r"(a[mi][0]), "r"(a[mi][1]), "r"(a[mi][2]), "r"(a[mi][3]),
                          "r"(bf[ni][0]), "r"(bf[ni][1]));
        }
    }

    // ---- epilogue: + b1[c] + x residual ----
    const int hw0 = h * Ww + col0 + wn * 32 + (lane & 3) * 2;
    #pragma unroll
    for (int mi = 0; mi < 4; mi++) {
        int cb = wm * 64 + mi * 16 + (lane >> 2);
        #pragma unroll
        for (int h8 = 0; h8 < 2; h8++) {
            int c = cb + h8 * 8;
            float bias = __ldg(b1 + c);
            size_t bofs = (((size_t)(b * Cc + c)) << 14) + hw0;
            #pragma unroll
            for (int ni = 0; ni < 4; ni++) {
                size_t o = bofs + ni * 8;
                float2 xv = *(const float2*)(x + o);
                float2 r;
                r.x = acc[mi][ni][h8 * 2 + 0] + bias + xv.x;
                r.y = acc[mi][ni][h8 * 2 + 1] + bias + xv.y;
                *(float2*)(out + o) = r;
            }
        }
    }
}

// ---------------------------------------------------------------------------
extern "C" void kernel_launch(void* const* d_in, const int* in_sizes, int n_in,
                              void* d_out, int out_size) {
    const float* x     = (const float*)d_in[0];
    const float* gamma = (const float*)d_in[1];
    const float* beta  = (const float*)d_in[2];
    const float* lbp   = (const float*)d_in[3];
    const float* w1    = (const float*)d_in[4];
    const float* b1    = (const float*)d_in[5];
    float* out = (float*)d_out;

    static bool attr_done = false;
    if (!attr_done) {
        cudaFuncSetAttribute(fused_kernel,
                             cudaFuncAttributeMaxDynamicSharedMemorySize,
                             SMEM_TOT);
        attr_done = true;
    }

    stats_part<<<dim3(Cc, Bn), 256>>>(x);
    finalize_stats<<<1, Cc>>>(gamma, beta);
    w1half<<<(Cc * NWw) / 1024, 256>>>(w1);
    prep_lwf<<<1, NWw>>>(lbp);
    fused_kernel<<<2048, 256, SMEM_TOT>>>(x, b1, out);
}

// round 13
// speedup vs baseline: 1.5850x; 1.5850x over previous
#include <cuda_runtime.h>
#include <cuda_fp16.h>
#include <cstdint>

#define Cc   256
#define Bn   8
#define Hh   128
#define Ww   128
#define NWw  512
#define HW   (Hh*Ww)
#define NPIX (Bn*HW)
#define EPSf 1e-5f

typedef unsigned long long ull;

// ---- scratch ---------------------------------------------------------------
__device__ float  g_ps [Cc*Bn];
__device__ float  g_ps2[Cc*Bn];
__device__ float  g_scale[Cc];
__device__ float  g_shift[Cc];
__device__ __half g_w1h[Cc * NWw];               // [c][j]  A operand (K-major)
__device__ __half g_y2[(size_t)NWw * NPIX];      // [j][pixel]  B operand

__device__ __forceinline__ uint32_t smem_u32(const void* p) {
    uint32_t a;
    asm("{ .reg .u64 t; cvta.to.shared.u64 t, %1; cvt.u32.u64 %0, t; }"
        : "=r"(a) : "l"(p));
    return a;
}

#define PACK2(d, lo, hi) asm("mov.b64 %0, {%1, %2};" : "=l"(d) : "f"(lo), "f"(hi))
#define PACKB(d, v)      asm("mov.b64 %0, {%1, %1};" : "=l"(d) : "f"(v))
#define UNPACK2(lo, hi, s) asm("mov.b64 {%0, %1}, %2;" : "=f"(lo), "=f"(hi) : "l"(s))
#define MUL2(d, a, b)    asm("mul.rn.f32x2 %0, %1, %2;" : "=l"(d) : "l"(a), "l"(b))
#define FMA2(acc, a, b)  asm("fma.rn.f32x2 %0, %1, %2, %0;" : "+l"(acc) : "l"(a), "l"(b))

// ---------------------------------------------------------------------------
// Stats (2-stage, deterministic)
// ---------------------------------------------------------------------------
__global__ __launch_bounds__(256) void stats_part(const float* __restrict__ x) {
    int c = blockIdx.x, b = blockIdx.y, tid = threadIdx.x;
    const float4* p = (const float4*)(x + ((size_t)(b * Cc + c)) * HW);
    float s = 0.f, s2 = 0.f;
    #pragma unroll 4
    for (int i = tid; i < HW / 4; i += 256) {
        float4 v = __ldg(p + i);
        s  += v.x + v.y + v.z + v.w;
        s2 += v.x*v.x + v.y*v.y + v.z*v.z + v.w*v.w;
    }
    __shared__ float sh[256], sh2[256];
    sh[tid] = s; sh2[tid] = s2;
    __syncthreads();
    for (int off = 128; off > 0; off >>= 1) {
        if (tid < off) { sh[tid] += sh[tid+off]; sh2[tid] += sh2[tid+off]; }
        __syncthreads();
    }
    if (tid == 0) { g_ps[c*Bn + b] = sh[0]; g_ps2[c*Bn + b] = sh2[0]; }
}

__global__ void finalize_stats(const float* __restrict__ gamma,
                               const float* __restrict__ beta) {
    int c = threadIdx.x;
    float s = 0.f, s2 = 0.f;
    #pragma unroll
    for (int b = 0; b < Bn; b++) { s += g_ps[c*Bn+b]; s2 += g_ps2[c*Bn+b]; }
    float n = (float)(Bn * HW);
    float mean = s / n;
    float var  = s2 / n - mean * mean;
    float sc   = gamma[c] * rsqrtf(var + EPSf);
    g_scale[c] = sc;
    g_shift[c] = beta[c] - mean * sc;
}

__global__ void w1half(const float* __restrict__ w1) {
    int i = (blockIdx.x * 256 + threadIdx.x) * 4;
    float4 v = __ldg((const float4*)(w1 + i));
    __half2 a = __floats2half2_rn(v.x, v.y);
    __half2 b = __floats2half2_rn(v.z, v.w);
    uint2 o = make_uint2(*(uint32_t*)&a, *(uint32_t*)&b);
    *(uint2*)(g_w1h + i) = o;
}

// ---------------------------------------------------------------------------
// Kernel 2 (v8, unchanged from R11): BN -> dw3x3 -> relu -> fp16 y2[j][pixel]
// ---------------------------------------------------------------------------
__global__ __launch_bounds__(256, 3)
void dw_kernel(const float* __restrict__ x, const float* __restrict__ lbp) {
    __shared__ float xs[4][18][136];           // 39168 B
    __shared__ float lw[8][9];

    const int tid   = threadIdx.x;
    const int chunk = blockIdx.x;              // 0..63 (4-ch chunks)
    const int h0    = blockIdx.y * 16;         // 16-row strip
    const int b     = blockIdx.z;
    const int cbase = chunk * 4;
    const int jbase = chunk * 8;

    if (tid < 144) {
        int ci = tid / 36, r2 = tid - ci * 36;
        int rr = r2 >> 1, side = r2 & 1;
        xs[ci][rr][side ? 132 : 3] = 0.f;
    }
    if (tid < 72) ((float*)lw)[tid] = __ldg(lbp + jbase * 9 + tid);

    #pragma unroll
    for (int i = 0; i < 9; i++) {
        int idx = tid + i * 256;
        int ci  = idx / 576;
        int rem = idx - ci * 576;
        int rr  = rem >> 5, q = rem & 31;
        int hh  = h0 - 1 + rr;
        float4 w = make_float4(0.f, 0.f, 0.f, 0.f);
        if ((unsigned)hh < (unsigned)Hh) {
            float sc = g_scale[cbase + ci];
            float sf = g_shift[cbase + ci];
            float4 v = __ldg((const float4*)(x + ((size_t)(b * Cc + cbase + ci)) * HW)
                             + hh * 32 + q);
            w.x = fmaf(v.x, sc, sf);
            w.y = fmaf(v.y, sc, sf);
            w.z = fmaf(v.z, sc, sf);
            w.w = fmaf(v.w, sc, sf);
        }
        *(float4*)&xs[ci][rr][4 + 4 * q] = w;
    }
    __syncthreads();

    const int pp = tid & 63;
    const int ci = tid >> 6;
    const int jl = ci * 2;
    const int px = pp * 2;

    ull pw0[9], pw1[9];
    #pragma unroll
    for (int t = 0; t < 9; t++) {
        PACKB(pw0[t], lw[jl][t]);
        PACKB(pw1[t], lw[jl + 1][t]);
    }

    const float* xr = &xs[ci][0][0];
    const int e = 4 + px;

    ull Ta0, Ta1, Ta2, Tb0, Tb1, Tb2;
    {
        float m1 = xr[e - 1];
        Ta1 = *(const ull*)&xr[e];
        float p2 = xr[e + 2];
        float mlo, mhi; UNPACK2(mlo, mhi, Ta1);
        PACK2(Ta0, m1, mlo);
        PACK2(Ta2, mhi, p2);
        m1  = xr[136 + e - 1];
        Tb1 = *(const ull*)&xr[136 + e];
        p2  = xr[136 + e + 2];
        UNPACK2(mlo, mhi, Tb1);
        PACK2(Tb0, m1, mlo);
        PACK2(Tb2, mhi, p2);
    }

    const __half2 zero2 = __floats2half2_rn(0.f, 0.f);
    __half2* y0p = (__half2*)(g_y2 + (size_t)(jbase + jl) * NPIX
                              + (size_t)b * HW + (size_t)h0 * Ww + px);
    __half2* y1p = (__half2*)((__half*)y0p + NPIX);

    #pragma unroll
    for (int r = 0; r < 16; r++) {
        const float* rc = xr + (r + 2) * 136 + e;
        float m1 = rc[-1];
        ull Tc1 = *(const ull*)rc;
        float p2 = rc[2];
        float mlo, mhi; UNPACK2(mlo, mhi, Tc1);
        ull Tc0, Tc2;
        PACK2(Tc0, m1, mlo);
        PACK2(Tc2, mhi, p2);

        ull a0, a1;
        MUL2(a0, pw0[0], Ta0);          MUL2(a1, pw1[0], Ta0);
        FMA2(a0, pw0[1], Ta1);          FMA2(a1, pw1[1], Ta1);
        FMA2(a0, pw0[2], Ta2);          FMA2(a1, pw1[2], Ta2);
        FMA2(a0, pw0[3], Tb0);          FMA2(a1, pw1[3], Tb0);
        FMA2(a0, pw0[4], Tb1);          FMA2(a1, pw1[4], Tb1);
        FMA2(a0, pw0[5], Tb2);          FMA2(a1, pw1[5], Tb2);
        FMA2(a0, pw0[6], Tc0);          FMA2(a1, pw1[6], Tc0);
        FMA2(a0, pw0[7], Tc1);          FMA2(a1, pw1[7], Tc1);
        FMA2(a0, pw0[8], Tc2);          FMA2(a1, pw1[8], Tc2);

        float s0l, s0h, s1l, s1h;
        UNPACK2(s0l, s0h, a0);
        UNPACK2(s1l, s1h, a1);
        y0p[r * 64] = __hmax2(__floats2half2_rn(s0l, s0h), zero2);
        y1p[r * 64] = __hmax2(__floats2half2_rn(s1l, s1h), zero2);

        Ta0 = Tb0; Ta1 = Tb1; Ta2 = Tb2;
        Tb0 = Tc0; Tb1 = Tc1; Tb2 = Tc2;
    }
}

// ---------------------------------------------------------------------------
// Kernel 3 (v3): HMMA GEMM, 3-stage cp.async pipeline, ONE sync per chunk.
// Block tile 128(M) x 128(N), K=512 in 8 chunks of 64; 8 warps (2x4), 64x32.
// ---------------------------------------------------------------------------
#define STG_BYTES 32768   // per stage: A 16KB + B 16KB
#define NSTG 3

__global__ __launch_bounds__(256)
void gemm_kernel(const float* __restrict__ x, const float* __restrict__ b1,
                 float* __restrict__ out) {
    extern __shared__ __align__(1024) char dsm[];
    const uint32_t s0 = smem_u32(dsm);

    const int tid  = threadIdx.x;
    const int wid  = tid >> 5, lane = tid & 31;
    const int wm   = wid & 1;
    const int wn   = wid >> 1;
    const int mt   = blockIdx.x;
    const size_t p0 = (size_t)blockIdx.y * 128;

    float acc[4][4][4];
    #pragma unroll
    for (int mi = 0; mi < 4; mi++)
        #pragma unroll
        for (int ni = 0; ni < 4; ni++)
            #pragma unroll
            for (int q = 0; q < 4; q++) acc[mi][ni][q] = 0.f;

    const __half* wsrc = g_w1h + (size_t)mt * 128 * NWw;
    const int lrow = tid >> 3, lu = tid & 7;     // A fill coords
    const int bkr  = tid >> 4, bu = tid & 15;    // B fill coords

    auto fill = [&](int st, int kc) {
        const uint32_t sA = s0 + st * STG_BYTES;
        const uint32_t sB = sA + 16384;
        const int k0 = kc * 64;
        #pragma unroll
        for (int i = 0; i < 4; i++) {            // A: 128 rows x 8 x 16B
            int row = lrow + i * 32;
            uint32_t sw = ((lu ^ (row & 7)) << 4) + row * 128;
            const __half* srcA = wsrc + (size_t)row * NWw + k0 + lu * 8;
            asm volatile("cp.async.cg.shared.global [%0], [%1], 16;"
                         :: "r"(sA + sw), "l"(srcA));
        }
        #pragma unroll
        for (int i = 0; i < 4; i++) {            // B: 64 k-rows x 16 x 16B
            int kr = bkr + i * 16;
            uint32_t dst = sB + kr * 256 + ((bu ^ (kr & 7)) << 4);
            const __half* srcB =
                g_y2 + (size_t)(k0 + kr) * NPIX + p0 + bu * 8;
            asm volatile("cp.async.cg.shared.global [%0], [%1], 16;"
                         :: "r"(dst), "l"(srcB));
        }
        asm volatile("cp.async.commit_group;");
    };

    fill(0, 0);
    fill(1, 1);

    int st = 0;
    for (int kc = 0; kc < 8; kc++) {
        if (kc < 7) asm volatile("cp.async.wait_group 1;");
        else        asm volatile("cp.async.wait_group 0;");
        __syncthreads();   // also orders: prev reads of stage (st+2)%3 done

        if (kc < 6) {
            int st2 = st + 2; if (st2 >= NSTG) st2 -= NSTG;
            fill(st2, kc + 2);
        }

        const uint32_t sA = s0 + st * STG_BYTES;
        const uint32_t sB = sA + 16384;

        #pragma unroll
        for (int ks = 0; ks < 4; ks++) {
            uint32_t a[4][4], bf[4][2];
            #pragma unroll
            for (int mi = 0; mi < 4; mi++) {
                int row = wm * 64 + mi * 16 + (lane & 15);
                uint32_t ad = sA + row * 128 + (((ks * 2 + (lane >> 4)) ^ (row & 7)) << 4);
                asm volatile(
                    "ldmatrix.sync.aligned.m8n8.x4.shared.b16 {%0,%1,%2,%3}, [%4];"
                    : "=r"(a[mi][0]), "=r"(a[mi][1]), "=r"(a[mi][2]), "=r"(a[mi][3])
                    : "r"(ad));
            }
            #pragma unroll
            for (int ni = 0; ni < 4; ni++) {
                int kr = ks * 16 + (lane & 15);
                uint32_t uu = wn * 4 + ni;
                uint32_t bd = sB + kr * 256 + ((uu ^ (kr & 7)) << 4);
                asm volatile(
                    "ldmatrix.sync.aligned.m8n8.x2.trans.shared.b16 {%0,%1}, [%2];"
                    : "=r"(bf[ni][0]), "=r"(bf[ni][1]) : "r"(bd));
            }
            #pragma unroll
            for (int mi = 0; mi < 4; mi++)
                #pragma unroll
                for (int ni = 0; ni < 4; ni++)
                    asm volatile(
                        "mma.sync.aligned.m16n8k16.row.col.f32.f16.f16.f32 "
                        "{%0,%1,%2,%3}, {%4,%5,%6,%7}, {%8,%9}, {%0,%1,%2,%3};"
                        : "+f"(acc[mi][ni][0]), "+f"(acc[mi][ni][1]),
                          "+f"(acc[mi][ni][2]), "+f"(acc[mi][ni][3])
                        : "r"(a[mi][0]), "r"(a[mi][1]), "r"(a[mi][2]), "r"(a[mi][3]),
                          "r"(bf[ni][0]), "r"(bf[ni][1]));
        }
        if (++st >= NSTG) st = 0;
    }

    // epilogue: + b1[c] + x residual
    const int bb  = (int)(p0 >> 14);
    const int hw0 = (int)(p0 & 16383) + wn * 32 + (lane & 3) * 2;
    #pragma unroll
    for (int mi = 0; mi < 4; mi++) {
        int cb = mt * 128 + wm * 64 + mi * 16 + (lane >> 2);
        #pragma unroll
        for (int h = 0; h < 2; h++) {
            int c = cb + h * 8;
            float bias = __ldg(b1 + c);
            size_t base = ((size_t)(bb * Cc + c)) * HW + hw0;
            #pragma unroll
            for (int ni = 0; ni < 4; ni++) {
                size_t o = base + ni * 8;
                float2 xv = *(const float2*)(x + o);
                float2 r;
                r.x = acc[mi][ni][h * 2 + 0] + bias + xv.x;
                r.y = acc[mi][ni][h * 2 + 1] + bias + xv.y;
                *(float2*)(out + o) = r;
            }
        }
    }
}

// ---------------------------------------------------------------------------
extern "C" void kernel_launch(void* const* d_in, const int* in_sizes, int n_in,
                              void* d_out, int out_size) {
    const float* x     = (const float*)d_in[0];
    const float* gamma = (const float*)d_in[1];
    const float* beta  = (const float*)d_in[2];
    const float* lbp   = (const float*)d_in[3];
    const float* w1    = (const float*)d_in[4];
    const float* b1    = (const float*)d_in[5];
    float* out = (float*)d_out;

    static bool attr_done = false;
    if (!attr_done) {
        cudaFuncSetAttribute(gemm_kernel,
                             cudaFuncAttributeMaxDynamicSharedMemorySize,
                             NSTG * STG_BYTES);
        attr_done = true;
    }

    stats_part<<<dim3(Cc, Bn), 256>>>(x);
    finalize_stats<<<1, Cc>>>(gamma, beta);
    w1half<<<(Cc * NWw) / 1024, 256>>>(w1);
    dw_kernel<<<dim3(64, 8, Bn), 256>>>(x, lbp);
    gemm_kernel<<<dim3(2, NPIX / 128), 256, NSTG * STG_BYTES>>>(x, b1, out);
}

// round 15
// speedup vs baseline: 1.6057x; 1.0130x over previous
#include <cuda_runtime.h>
#include <cuda_fp16.h>
#include <cstdint>

#define Cc   256
#define Bn   8
#define Hh   128
#define Ww   128
#define NWw  512
#define HW   (Hh*Ww)
#define NPIX (Bn*HW)
#define EPSf 1e-5f

typedef unsigned long long ull;

// ---- scratch ---------------------------------------------------------------
__device__ float  g_ps [Cc*Bn];
__device__ float  g_ps2[Cc*Bn];
__device__ float  g_scale[Cc];
__device__ float  g_shift[Cc];
__device__ __half g_w1h[Cc * NWw];               // [c][j]  A operand (K-major)
__device__ __half g_y2[(size_t)NWw * NPIX];      // [j][pixel]  B operand

__device__ __forceinline__ uint32_t smem_u32(const void* p) {
    uint32_t a;
    asm("{ .reg .u64 t; cvta.to.shared.u64 t, %1; cvt.u32.u64 %0, t; }"
        : "=r"(a) : "l"(p));
    return a;
}

#define PACK2(d, lo, hi) asm("mov.b64 %0, {%1, %2};" : "=l"(d) : "f"(lo), "f"(hi))
#define PACKB(d, v)      asm("mov.b64 %0, {%1, %1};" : "=l"(d) : "f"(v))
#define UNPACK2(lo, hi, s) asm("mov.b64 {%0, %1}, %2;" : "=f"(lo), "=f"(hi) : "l"(s))
#define MUL2(d, a, b)    asm("mul.rn.f32x2 %0, %1, %2;" : "=l"(d) : "l"(a), "l"(b))
#define FMA2(acc, a, b)  asm("fma.rn.f32x2 %0, %1, %2, %0;" : "+l"(acc) : "l"(a), "l"(b))

// ---------------------------------------------------------------------------
// Stats (2-stage, deterministic)
// ---------------------------------------------------------------------------
__global__ __launch_bounds__(256) void stats_part(const float* __restrict__ x) {
    int c = blockIdx.x, b = blockIdx.y, tid = threadIdx.x;
    const float4* p = (const float4*)(x + ((size_t)(b * Cc + c)) * HW);
    float s = 0.f, s2 = 0.f;
    #pragma unroll 4
    for (int i = tid; i < HW / 4; i += 256) {
        float4 v = __ldg(p + i);
        s  += v.x + v.y + v.z + v.w;
        s2 += v.x*v.x + v.y*v.y + v.z*v.z + v.w*v.w;
    }
    __shared__ float sh[256], sh2[256];
    sh[tid] = s; sh2[tid] = s2;
    __syncthreads();
    for (int off = 128; off > 0; off >>= 1) {
        if (tid < off) { sh[tid] += sh[tid+off]; sh2[tid] += sh2[tid+off]; }
        __syncthreads();
    }
    if (tid == 0) { g_ps[c*Bn + b] = sh[0]; g_ps2[c*Bn + b] = sh2[0]; }
}

// merged: w1 -> fp16 (all 128 blocks) + finalize scale/shift (block 0)
__global__ __launch_bounds__(256)
void prep_kernel(const float* __restrict__ gamma,
                 const float* __restrict__ beta,
                 const float* __restrict__ w1) {
    int i = (blockIdx.x * 256 + threadIdx.x) * 4;
    float4 v = __ldg((const float4*)(w1 + i));
    __half2 a = __floats2half2_rn(v.x, v.y);
    __half2 b = __floats2half2_rn(v.z, v.w);
    uint2 o = make_uint2(*(uint32_t*)&a, *(uint32_t*)&b);
    *(uint2*)(g_w1h + i) = o;

    if (blockIdx.x == 0) {
        int c = threadIdx.x;
        float s = 0.f, s2 = 0.f;
        #pragma unroll
        for (int bb = 0; bb < Bn; bb++) { s += g_ps[c*Bn+bb]; s2 += g_ps2[c*Bn+bb]; }
        float n = (float)(Bn * HW);
        float mean = s / n;
        float var  = s2 / n - mean * mean;
        float sc   = gamma[c] * rsqrtf(var + EPSf);
        g_scale[c] = sc;
        g_shift[c] = beta[c] - mean * sc;
    }
}

// ---------------------------------------------------------------------------
// Kernel 2 (v8, unchanged from R11/R13): BN -> dw3x3 -> relu -> fp16 y2[j][px]
// ---------------------------------------------------------------------------
__global__ __launch_bounds__(256, 3)
void dw_kernel(const float* __restrict__ x, const float* __restrict__ lbp) {
    __shared__ float xs[4][18][136];           // 39168 B
    __shared__ float lw[8][9];

    const int tid   = threadIdx.x;
    const int chunk = blockIdx.x;              // 0..63 (4-ch chunks)
    const int h0    = blockIdx.y * 16;         // 16-row strip
    const int b     = blockIdx.z;
    const int cbase = chunk * 4;
    const int jbase = chunk * 8;

    if (tid < 144) {
        int ci = tid / 36, r2 = tid - ci * 36;
        int rr = r2 >> 1, side = r2 & 1;
        xs[ci][rr][side ? 132 : 3] = 0.f;
    }
    if (tid < 72) ((float*)lw)[tid] = __ldg(lbp + jbase * 9 + tid);

    #pragma unroll
    for (int i = 0; i < 9; i++) {
        int idx = tid + i * 256;
        int ci  = idx / 576;
        int rem = idx - ci * 576;
        int rr  = rem >> 5, q = rem & 31;
        int hh  = h0 - 1 + rr;
        float4 w = make_float4(0.f, 0.f, 0.f, 0.f);
        if ((unsigned)hh < (unsigned)Hh) {
            float sc = g_scale[cbase + ci];
            float sf = g_shift[cbase + ci];
            float4 v = __ldg((const float4*)(x + ((size_t)(b * Cc + cbase + ci)) * HW)
                             + hh * 32 + q);
            w.x = fmaf(v.x, sc, sf);
            w.y = fmaf(v.y, sc, sf);
            w.z = fmaf(v.z, sc, sf);
            w.w = fmaf(v.w, sc, sf);
        }
        *(float4*)&xs[ci][rr][4 + 4 * q] = w;
    }
    __syncthreads();

    const int pp = tid & 63;
    const int ci = tid >> 6;
    const int jl = ci * 2;
    const int px = pp * 2;

    ull pw0[9], pw1[9];
    #pragma unroll
    for (int t = 0; t < 9; t++) {
        PACKB(pw0[t], lw[jl][t]);
        PACKB(pw1[t], lw[jl + 1][t]);
    }

    const float* xr = &xs[ci][0][0];
    const int e = 4 + px;

    ull Ta0, Ta1, Ta2, Tb0, Tb1, Tb2;
    {
        float m1 = xr[e - 1];
        Ta1 = *(const ull*)&xr[e];
        float p2 = xr[e + 2];
        float mlo, mhi; UNPACK2(mlo, mhi, Ta1);
        PACK2(Ta0, m1, mlo);
        PACK2(Ta2, mhi, p2);
        m1  = xr[136 + e - 1];
        Tb1 = *(const ull*)&xr[136 + e];
        p2  = xr[136 + e + 2];
        UNPACK2(mlo, mhi, Tb1);
        PACK2(Tb0, m1, mlo);
        PACK2(Tb2, mhi, p2);
    }

    const __half2 zero2 = __floats2half2_rn(0.f, 0.f);
    __half2* y0p = (__half2*)(g_y2 + (size_t)(jbase + jl) * NPIX
                              + (size_t)b * HW + (size_t)h0 * Ww + px);
    __half2* y1p = (__half2*)((__half*)y0p + NPIX);

    #pragma unroll
    for (int r = 0; r < 16; r++) {
        const float* rc = xr + (r + 2) * 136 + e;
        float m1 = rc[-1];
        ull Tc1 = *(const ull*)rc;
        float p2 = rc[2];
        float mlo, mhi; UNPACK2(mlo, mhi, Tc1);
        ull Tc0, Tc2;
        PACK2(Tc0, m1, mlo);
        PACK2(Tc2, mhi, p2);

        ull a0, a1;
        MUL2(a0, pw0[0], Ta0);          MUL2(a1, pw1[0], Ta0);
        FMA2(a0, pw0[1], Ta1);          FMA2(a1, pw1[1], Ta1);
        FMA2(a0, pw0[2], Ta2);          FMA2(a1, pw1[2], Ta2);
        FMA2(a0, pw0[3], Tb0);          FMA2(a1, pw1[3], Tb0);
        FMA2(a0, pw0[4], Tb1);          FMA2(a1, pw1[4], Tb1);
        FMA2(a0, pw0[5], Tb2);          FMA2(a1, pw1[5], Tb2);
        FMA2(a0, pw0[6], Tc0);          FMA2(a1, pw1[6], Tc0);
        FMA2(a0, pw0[7], Tc1);          FMA2(a1, pw1[7], Tc1);
        FMA2(a0, pw0[8], Tc2);          FMA2(a1, pw1[8], Tc2);

        float s0l, s0h, s1l, s1h;
        UNPACK2(s0l, s0h, a0);
        UNPACK2(s1l, s1h, a1);
        y0p[r * 64] = __hmax2(__floats2half2_rn(s0l, s0h), zero2);
        y1p[r * 64] = __hmax2(__floats2half2_rn(s1l, s1h), zero2);

        Ta0 = Tb0; Ta1 = Tb1; Ta2 = Tb2;
        Tb0 = Tc0; Tb1 = Tc1; Tb2 = Tc2;
    }
}

// ---------------------------------------------------------------------------
// Kernel 3 (v3, unchanged from R13): HMMA GEMM, 3-stage cp.async pipeline
// ---------------------------------------------------------------------------
#define STG_BYTES 32768   // per stage: A 16KB + B 16KB
#define NSTG 3

__global__ __launch_bounds__(256)
void gemm_kernel(const float* __restrict__ x, const float* __restrict__ b1,
                 float* __restrict__ out) {
    extern __shared__ __align__(1024) char dsm[];
    const uint32_t s0 = smem_u32(dsm);

    const int tid  = threadIdx.x;
    const int wid  = tid >> 5, lane = tid & 31;
    const int wm   = wid & 1;
    const int wn   = wid >> 1;
    const int mt   = blockIdx.x;
    const size_t p0 = (size_t)blockIdx.y * 128;

    float acc[4][4][4];
    #pragma unroll
    for (int mi = 0; mi < 4; mi++)
        #pragma unroll
        for (int ni = 0; ni < 4; ni++)
            #pragma unroll
            for (int q = 0; q < 4; q++) acc[mi][ni][q] = 0.f;

    const __half* wsrc = g_w1h + (size_t)mt * 128 * NWw;
    const int lrow = tid >> 3, lu = tid & 7;     // A fill coords
    const int bkr  = tid >> 4, bu = tid & 15;    // B fill coords

    auto fill = [&](int st, int kc) {
        const uint32_t sA = s0 + st * STG_BYTES;
        const uint32_t sB = sA + 16384;
        const int k0 = kc * 64;
        #pragma unroll
        for (int i = 0; i < 4; i++) {            // A: 128 rows x 8 x 16B
            int row = lrow + i * 32;
            uint32_t sw = ((lu ^ (row & 7)) << 4) + row * 128;
            const __half* srcA = wsrc + (size_t)row * NWw + k0 + lu * 8;
            asm volatile("cp.async.cg.shared.global [%0], [%1], 16;"
                         :: "r"(sA + sw), "l"(srcA));
        }
        #pragma unroll
        for (int i = 0; i < 4; i++) {            // B: 64 k-rows x 16 x 16B
            int kr = bkr + i * 16;
            uint32_t dst = sB + kr * 256 + ((bu ^ (kr & 7)) << 4);
            const __half* srcB =
                g_y2 + (size_t)(k0 + kr) * NPIX + p0 + bu * 8;
            asm volatile("cp.async.cg.shared.global [%0], [%1], 16;"
                         :: "r"(dst), "l"(srcB));
        }
        asm volatile("cp.async.commit_group;");
    };

    fill(0, 0);
    fill(1, 1);

    int st = 0;
    for (int kc = 0; kc < 8; kc++) {
        if (kc < 7) asm volatile("cp.async.wait_group 1;");
        else        asm volatile("cp.async.wait_group 0;");
        __syncthreads();

        if (kc < 6) {
            int st2 = st + 2; if (st2 >= NSTG) st2 -= NSTG;
            fill(st2, kc + 2);
        }

        const uint32_t sA = s0 + st * STG_BYTES;
        const uint32_t sB = sA + 16384;

        #pragma unroll
        for (int ks = 0; ks < 4; ks++) {
            uint32_t a[4][4], bf[4][2];
            #pragma unroll
            for (int mi = 0; mi < 4; mi++) {
                int row = wm * 64 + mi * 16 + (lane & 15);
                uint32_t ad = sA + row * 128 + (((ks * 2 + (lane >> 4)) ^ (row & 7)) << 4);
                asm volatile(
                    "ldmatrix.sync.aligned.m8n8.x4.shared.b16 {%0,%1,%2,%3}, [%4];"
                    : "=r"(a[mi][0]), "=r"(a[mi][1]), "=r"(a[mi][2]), "=r"(a[mi][3])
                    : "r"(ad));
            }
            #pragma unroll
            for (int ni = 0; ni < 4; ni++) {
                int kr = ks * 16 + (lane & 15);
                uint32_t uu = wn * 4 + ni;
                uint32_t bd = sB + kr * 256 + ((uu ^ (kr & 7)) << 4);
                asm volatile(
                    "ldmatrix.sync.aligned.m8n8.x2.trans.shared.b16 {%0,%1}, [%2];"
                    : "=r"(bf[ni][0]), "=r"(bf[ni][1]) : "r"(bd));
            }
            #pragma unroll
            for (int mi = 0; mi < 4; mi++)
                #pragma unroll
                for (int ni = 0; ni < 4; ni++)
                    asm volatile(
                        "mma.sync.aligned.m16n8k16.row.col.f32.f16.f16.f32 "
                        "{%0,%1,%2,%3}, {%4,%5,%6,%7}, {%8,%9}, {%0,%1,%2,%3};"
                        : "+f"(acc[mi][ni][0]), "+f"(acc[mi][ni][1]),
                          "+f"(acc[mi][ni][2]), "+f"(acc[mi][ni][3])
                        : "r"(a[mi][0]), "r"(a[mi][1]), "r"(a[mi][2]), "r"(a[mi][3]),
                          "r"(bf[ni][0]), "r"(bf[ni][1]));
        }
        if (++st >= NSTG) st = 0;
    }

    // epilogue: + b1[c] + x residual
    const int bb  = (int)(p0 >> 14);
    const int hw0 = (int)(p0 & 16383) + wn * 32 + (lane & 3) * 2;
    #pragma unroll
    for (int mi = 0; mi < 4; mi++) {
        int cb = mt * 128 + wm * 64 + mi * 16 + (lane >> 2);
        #pragma unroll
        for (int h = 0; h < 2; h++) {
            int c = cb + h * 8;
            float bias = __ldg(b1 + c);
            size_t base = ((size_t)(bb * Cc + c)) * HW + hw0;
            #pragma unroll
            for (int ni = 0; ni < 4; ni++) {
                size_t o = base + ni * 8;
                float2 xv = *(const float2*)(x + o);
                float2 r;
                r.x = acc[mi][ni][h * 2 + 0] + bias + xv.x;
                r.y = acc[mi][ni][h * 2 + 1] + bias + xv.y;
                *(float2*)(out + o) = r;
            }
        }
    }
}

// ---------------------------------------------------------------------------
extern "C" void kernel_launch(void* const* d_in, const int* in_sizes, int n_in,
                              void* d_out, int out_size) {
    const float* x     = (const float*)d_in[0];
    const float* gamma = (const float*)d_in[1];
    const float* beta  = (const float*)d_in[2];
    const float* lbp   = (const float*)d_in[3];
    const float* w1    = (const float*)d_in[4];
    const float* b1    = (const float*)d_in[5];
    float* out = (float*)d_out;

    static bool attr_done = false;
    if (!attr_done) {
        cudaFuncSetAttribute(gemm_kernel,
                             cudaFuncAttributeMaxDynamicSharedMemorySize,
                             NSTG * STG_BYTES);
        attr_done = true;
    }

    stats_part<<<dim3(Cc, Bn), 256>>>(x);
    prep_kernel<<<(Cc * NWw) / 1024, 256>>>(gamma, beta, w1);
    dw_kernel<<<dim3(64, 8, Bn), 256>>>(x, lbp);
    gemm_kernel<<<dim3(2, NPIX / 128), 256, NSTG * STG_BYTES>>>(x, b1, out);
}